// round 4
// baseline (speedup 1.0000x reference)
#include <cuda_runtime.h>

#define NQ      8
#define KCODES  1024
#define DIM     64
#define TOKENS  65536
#define TILE    64              // codes per smem tile
#define CTA     64              // threads per CTA
#define T       4               // tokens per thread
#define TOK_CTA (CTA * T)       // 256 tokens per CTA

typedef unsigned long long u64;

// per-stage codebook squared norms, bit-exact sequential order
__device__ float g_csq[NQ * KCODES];

__device__ __forceinline__ void ffma2(u64& acc, u64 a, u64 b) {
    asm("fma.rn.f32x2 %0, %1, %2, %0;" : "+l"(acc) : "l"(a), "l"(b));
}
__device__ __forceinline__ u64 dup2(float v) {
    u64 r;
    asm("mov.b64 %0, {%1, %1};" : "=l"(r) : "f"(v));
    return r;
}
__device__ __forceinline__ void unpack2(float& lo, float& hi, u64 v) {
    asm("mov.b64 {%0, %1}, %2;" : "=f"(lo), "=f"(hi) : "l"(v));
}

// c_sq[k] = sequential d-ascending fadd(fmul) — unchanged from passing kernel
__global__ void csq_kernel(const float* __restrict__ cb) {
    int r = blockIdx.x * blockDim.x + threadIdx.x;
    const float4* row = reinterpret_cast<const float4*>(cb + (size_t)r * DIM);
    float s = 0.f;
#pragma unroll
    for (int i = 0; i < DIM / 4; i++) {
        float4 v = row[i];
        s = __fadd_rn(s, __fmul_rn(v.x, v.x));
        s = __fadd_rn(s, __fmul_rn(v.y, v.y));
        s = __fadd_rn(s, __fmul_rn(v.z, v.z));
        s = __fadd_rn(s, __fmul_rn(v.w, v.w));
    }
    g_csq[r] = s;
}

__global__ void __launch_bounds__(CTA)
rvq_kernel(const float* __restrict__ x,
           const float* __restrict__ cb,
           float* __restrict__ out) {
    extern __shared__ float sm[];
    float* smr = sm;                       // [DIM][TOK_CTA]  residuals (thread-private columns)
    float* smT = sm + DIM * TOK_CTA;       // [DIM][TILE]     transposed codebook tile
    float* scq = smT + DIM * TILE;         // [TILE]

    const int tid  = threadIdx.x;
    const int base = blockIdx.x * TOK_CTA;

    float rsq[T];
    float best[T];
    int   bk[T];

    // ---- init: residual = x (to smem), rsq = sequential fadd(fmul) over x ----
#pragma unroll
    for (int t = 0; t < T; t++) {
        const int   off = tid + CTA * t;
        const float4* xr = reinterpret_cast<const float4*>(
            x + (size_t)(base + off) * DIM);
        float s = 0.f;
#pragma unroll
        for (int p = 0; p < DIM / 4; p++) {
            float4 v = xr[p];
            smr[(4 * p + 0) * TOK_CTA + off] = v.x; s = __fadd_rn(s, __fmul_rn(v.x, v.x));
            smr[(4 * p + 1) * TOK_CTA + off] = v.y; s = __fadd_rn(s, __fmul_rn(v.y, v.y));
            smr[(4 * p + 2) * TOK_CTA + off] = v.z; s = __fadd_rn(s, __fmul_rn(v.z, v.z));
            smr[(4 * p + 3) * TOK_CTA + off] = v.w; s = __fadd_rn(s, __fmul_rn(v.w, v.w));
        }
        rsq[t] = s;
    }

#pragma unroll 1
    for (int q = 0; q < NQ; q++) {
        const float* cbq = cb + (size_t)q * KCODES * DIM;
#pragma unroll
        for (int t = 0; t < T; t++) {
            best[t] = __int_as_float(0x7f800000);
            bk[t]   = 0;
        }

#pragma unroll 1
        for (int c = 0; c < KCODES / TILE; c++) {
            __syncthreads();
            // tile load: thread tid owns code row c*TILE+tid, writes transposed
            {
                const float4* src = reinterpret_cast<const float4*>(
                    cbq + (size_t)(c * TILE + tid) * DIM);
#pragma unroll
                for (int i = 0; i < DIM / 4; i++) {
                    float4 v = src[i];
                    smT[(4 * i + 0) * TILE + tid] = v.x;
                    smT[(4 * i + 1) * TILE + tid] = v.y;
                    smT[(4 * i + 2) * TILE + tid] = v.z;
                    smT[(4 * i + 3) * TILE + tid] = v.w;
                }
                scq[tid] = g_csq[q * KCODES + c * TILE + tid];
            }
            __syncthreads();

#pragma unroll
            for (int g = 0; g < TILE; g += 32) {
                u64 acc[T][16];
#pragma unroll
                for (int t = 0; t < T; t++)
#pragma unroll
                    for (int j = 0; j < 16; j++) acc[t][j] = 0ull;

#pragma unroll 2
                for (int d = 0; d < DIM; d++) {
                    const ulonglong2* row =
                        reinterpret_cast<const ulonglong2*>(smT + d * TILE + g);
                    u64 rd[T];
#pragma unroll
                    for (int t = 0; t < T; t++)
                        rd[t] = dup2(smr[d * TOK_CTA + tid + CTA * t]);
#pragma unroll
                    for (int m = 0; m < 8; m++) {
                        ulonglong2 cv = row[m];    // LDS.128 broadcast, reused 4x
#pragma unroll
                        for (int t = 0; t < T; t++) {
                            ffma2(acc[t][2 * m],     rd[t], cv.x);
                            ffma2(acc[t][2 * m + 1], rd[t], cv.y);
                        }
                    }
                }

                // dist = (r_sq - 2*dot) + c_sq, exact op order; strict-< first-min
#pragma unroll
                for (int j = 0; j < 16; j++) {
                    float cs0 = scq[g + 2 * j];
                    float cs1 = scq[g + 2 * j + 1];
                    int   k0  = c * TILE + g + 2 * j;
#pragma unroll
                    for (int t = 0; t < T; t++) {
                        float d0, d1;
                        unpack2(d0, d1, acc[t][j]);
                        float s0 = __fadd_rn(__fsub_rn(rsq[t], __fmul_rn(2.0f, d0)), cs0);
                        float s1 = __fadd_rn(__fsub_rn(rsq[t], __fmul_rn(2.0f, d1)), cs1);
                        if (s0 < best[t]) { best[t] = s0; bk[t] = k0; }
                        if (s1 < best[t]) { best[t] = s1; bk[t] = k0 + 1; }
                    }
                }
            }
        }

        // residual update (exact fsub) + next-stage rsq in the same pass
#pragma unroll
        for (int t = 0; t < T; t++) {
            const int off = tid + CTA * t;
            const float4* crow = reinterpret_cast<const float4*>(
                cbq + (size_t)bk[t] * DIM);
            float s = 0.f;
#pragma unroll
            for (int p = 0; p < DIM / 4; p++) {
                float4 v = crow[p];
                float r0 = smr[(4 * p + 0) * TOK_CTA + off];
                float r1 = smr[(4 * p + 1) * TOK_CTA + off];
                float r2 = smr[(4 * p + 2) * TOK_CTA + off];
                float r3 = smr[(4 * p + 3) * TOK_CTA + off];
                r0 = __fsub_rn(r0, v.x);
                r1 = __fsub_rn(r1, v.y);
                r2 = __fsub_rn(r2, v.z);
                r3 = __fsub_rn(r3, v.w);
                smr[(4 * p + 0) * TOK_CTA + off] = r0;
                smr[(4 * p + 1) * TOK_CTA + off] = r1;
                smr[(4 * p + 2) * TOK_CTA + off] = r2;
                smr[(4 * p + 3) * TOK_CTA + off] = r3;
                s = __fadd_rn(s, __fmul_rn(r0, r0));
                s = __fadd_rn(s, __fmul_rn(r1, r1));
                s = __fadd_rn(s, __fmul_rn(r2, r2));
                s = __fadd_rn(s, __fmul_rn(r3, r3));
            }
            rsq[t] = s;
        }
    }

    // out = x - residual_final
#pragma unroll
    for (int t = 0; t < T; t++) {
        const int off = tid + CTA * t;
        const float4* xr = reinterpret_cast<const float4*>(
            x + (size_t)(base + off) * DIM);
        float4* orow = reinterpret_cast<float4*>(
            out + (size_t)(base + off) * DIM);
#pragma unroll
        for (int p = 0; p < DIM / 4; p++) {
            float4 v = xr[p];
            v.x = __fsub_rn(v.x, smr[(4 * p + 0) * TOK_CTA + off]);
            v.y = __fsub_rn(v.y, smr[(4 * p + 1) * TOK_CTA + off]);
            v.z = __fsub_rn(v.z, smr[(4 * p + 2) * TOK_CTA + off]);
            v.w = __fsub_rn(v.w, smr[(4 * p + 3) * TOK_CTA + off]);
            orow[p] = v;
        }
    }
}

extern "C" void kernel_launch(void* const* d_in, const int* in_sizes, int n_in,
                              void* d_out, int out_size) {
    const float* x;
    const float* cb;
    if (in_sizes[0] == NQ * KCODES * DIM) {
        cb = (const float*)d_in[0];
        x  = (const float*)d_in[1];
    } else {
        x  = (const float*)d_in[0];
        cb = (const float*)d_in[1];
    }
    float* out = (float*)d_out;

    const int smem_bytes = (DIM * TOK_CTA + DIM * TILE + TILE) * sizeof(float);
    cudaFuncSetAttribute(rvq_kernel,
                         cudaFuncAttributeMaxDynamicSharedMemorySize, smem_bytes);

    csq_kernel<<<(NQ * KCODES) / 128, 128>>>(cb);
    rvq_kernel<<<TOKENS / TOK_CTA, CTA, smem_bytes>>>(x, cb, out);
}

// round 5
// speedup vs baseline: 1.0062x; 1.0062x over previous
#include <cuda_runtime.h>

#define NQ      8
#define KCODES  1024
#define DIM     64
#define TOKENS  65536
#define TILE    64              // codes per smem tile
#define CTA     64              // threads per CTA
#define T       4               // tokens per thread
#define BLK     16              // codes per accumulator block
#define TOK_CTA (CTA * T)       // 256 tokens per CTA

typedef unsigned long long u64;

__device__ float g_csq[NQ * KCODES];

__device__ __forceinline__ void ffma2(u64& acc, u64 a, u64 b) {
    asm("fma.rn.f32x2 %0, %1, %2, %0;" : "+l"(acc) : "l"(a), "l"(b));
}
__device__ __forceinline__ u64 dup2(float v) {
    u64 r;
    asm("mov.b64 %0, {%1, %1};" : "=l"(r) : "f"(v));
    return r;
}
__device__ __forceinline__ void unpack2(float& lo, float& hi, u64 v) {
    asm("mov.b64 {%0, %1}, %2;" : "=f"(lo), "=f"(hi) : "l"(v));
}

// c_sq[k] = sequential d-ascending fadd(fmul) — bit-exact recipe (unchanged)
__global__ void csq_kernel(const float* __restrict__ cb) {
    int r = blockIdx.x * blockDim.x + threadIdx.x;
    const float4* row = reinterpret_cast<const float4*>(cb + (size_t)r * DIM);
    float s = 0.f;
#pragma unroll
    for (int i = 0; i < DIM / 4; i++) {
        float4 v = row[i];
        s = __fadd_rn(s, __fmul_rn(v.x, v.x));
        s = __fadd_rn(s, __fmul_rn(v.y, v.y));
        s = __fadd_rn(s, __fmul_rn(v.z, v.z));
        s = __fadd_rn(s, __fmul_rn(v.w, v.w));
    }
    g_csq[r] = s;
}

__global__ void __launch_bounds__(CTA, 2)
rvq_kernel(const float* __restrict__ x,
           const float* __restrict__ cb,
           float* __restrict__ out) {
    extern __shared__ float sm[];
    float* smr = sm;                       // [DIM][TOK_CTA] residuals
    float* smT = sm + DIM * TOK_CTA;       // [DIM][TILE] transposed codebook tile
    float* scq = smT + DIM * TILE;         // [TILE]

    const int tid  = threadIdx.x;
    const int base = blockIdx.x * TOK_CTA;

    float rsq[T];
    float best[T];
    int   bk[T];

    // init: residual = x (smem), rsq sequential fadd(fmul)
#pragma unroll
    for (int t = 0; t < T; t++) {
        const int off = tid + CTA * t;
        const float4* xr = reinterpret_cast<const float4*>(
            x + (size_t)(base + off) * DIM);
        float s = 0.f;
#pragma unroll
        for (int p = 0; p < DIM / 4; p++) {
            float4 v = xr[p];
            smr[(4 * p + 0) * TOK_CTA + off] = v.x; s = __fadd_rn(s, __fmul_rn(v.x, v.x));
            smr[(4 * p + 1) * TOK_CTA + off] = v.y; s = __fadd_rn(s, __fmul_rn(v.y, v.y));
            smr[(4 * p + 2) * TOK_CTA + off] = v.z; s = __fadd_rn(s, __fmul_rn(v.z, v.z));
            smr[(4 * p + 3) * TOK_CTA + off] = v.w; s = __fadd_rn(s, __fmul_rn(v.w, v.w));
        }
        rsq[t] = s;
    }

#pragma unroll 1
    for (int q = 0; q < NQ; q++) {
        const float* cbq = cb + (size_t)q * KCODES * DIM;
#pragma unroll
        for (int t = 0; t < T; t++) {
            best[t] = __int_as_float(0x7f800000);
            bk[t]   = 0;
        }

#pragma unroll 1
        for (int c = 0; c < KCODES / TILE; c++) {
            __syncthreads();
            {
                const float4* src = reinterpret_cast<const float4*>(
                    cbq + (size_t)(c * TILE + tid) * DIM);
#pragma unroll
                for (int i = 0; i < DIM / 4; i++) {
                    float4 v = src[i];
                    smT[(4 * i + 0) * TILE + tid] = v.x;
                    smT[(4 * i + 1) * TILE + tid] = v.y;
                    smT[(4 * i + 2) * TILE + tid] = v.z;
                    smT[(4 * i + 3) * TILE + tid] = v.w;
                }
                scq[tid] = g_csq[q * KCODES + c * TILE + tid];
            }
            __syncthreads();

#pragma unroll 1
            for (int g = 0; g < TILE; g += BLK) {
                u64 acc[T][BLK / 2];               // 4 x 8 u64 = 64 regs
#pragma unroll
                for (int t = 0; t < T; t++)
#pragma unroll
                    for (int j = 0; j < BLK / 2; j++) acc[t][j] = 0ull;

#pragma unroll 4
                for (int d = 0; d < DIM; d++) {
                    u64 rd[T];
#pragma unroll
                    for (int t = 0; t < T; t++)
                        rd[t] = dup2(smr[d * TOK_CTA + tid + CTA * t]);
                    const ulonglong2* row =
                        reinterpret_cast<const ulonglong2*>(smT + d * TILE + g);
                    ulonglong2 c0 = row[0];   // codes g..g+3
                    ulonglong2 c1 = row[1];   // g+4..g+7
                    ulonglong2 c2 = row[2];   // g+8..g+11
                    ulonglong2 c3 = row[3];   // g+12..g+15
#pragma unroll
                    for (int t = 0; t < T; t++) {
                        ffma2(acc[t][0], rd[t], c0.x);
                        ffma2(acc[t][1], rd[t], c0.y);
                        ffma2(acc[t][2], rd[t], c1.x);
                        ffma2(acc[t][3], rd[t], c1.y);
                        ffma2(acc[t][4], rd[t], c2.x);
                        ffma2(acc[t][5], rd[t], c2.y);
                        ffma2(acc[t][6], rd[t], c3.x);
                        ffma2(acc[t][7], rd[t], c3.y);
                    }
                }

                // dist = (r_sq - 2*dot) + c_sq; strict-< first-min, k ascending
#pragma unroll
                for (int j = 0; j < BLK / 2; j++) {
                    float cs0 = scq[g + 2 * j];
                    float cs1 = scq[g + 2 * j + 1];
                    int   k0  = c * TILE + g + 2 * j;
#pragma unroll
                    for (int t = 0; t < T; t++) {
                        float d0, d1;
                        unpack2(d0, d1, acc[t][j]);
                        float s0 = __fadd_rn(__fsub_rn(rsq[t], __fmul_rn(2.0f, d0)), cs0);
                        float s1 = __fadd_rn(__fsub_rn(rsq[t], __fmul_rn(2.0f, d1)), cs1);
                        if (s0 < best[t]) { best[t] = s0; bk[t] = k0; }
                        if (s1 < best[t]) { best[t] = s1; bk[t] = k0 + 1; }
                    }
                }
            }
        }

        // residual update (exact fsub) + next-stage rsq, same order as before
#pragma unroll
        for (int t = 0; t < T; t++) {
            const int off = tid + CTA * t;
            const float4* crow = reinterpret_cast<const float4*>(
                cbq + (size_t)bk[t] * DIM);
            float s = 0.f;
#pragma unroll
            for (int p = 0; p < DIM / 4; p++) {
                float4 v = crow[p];
                float r0 = __fsub_rn(smr[(4 * p + 0) * TOK_CTA + off], v.x);
                float r1 = __fsub_rn(smr[(4 * p + 1) * TOK_CTA + off], v.y);
                float r2 = __fsub_rn(smr[(4 * p + 2) * TOK_CTA + off], v.z);
                float r3 = __fsub_rn(smr[(4 * p + 3) * TOK_CTA + off], v.w);
                smr[(4 * p + 0) * TOK_CTA + off] = r0;
                smr[(4 * p + 1) * TOK_CTA + off] = r1;
                smr[(4 * p + 2) * TOK_CTA + off] = r2;
                smr[(4 * p + 3) * TOK_CTA + off] = r3;
                s = __fadd_rn(s, __fmul_rn(r0, r0));
                s = __fadd_rn(s, __fmul_rn(r1, r1));
                s = __fadd_rn(s, __fmul_rn(r2, r2));
                s = __fadd_rn(s, __fmul_rn(r3, r3));
            }
            rsq[t] = s;
        }
    }

    // out = x - residual_final
#pragma unroll
    for (int t = 0; t < T; t++) {
        const int off = tid + CTA * t;
        const float4* xr = reinterpret_cast<const float4*>(
            x + (size_t)(base + off) * DIM);
        float4* orow = reinterpret_cast<float4*>(
            out + (size_t)(base + off) * DIM);
#pragma unroll
        for (int p = 0; p < DIM / 4; p++) {
            float4 v = xr[p];
            v.x = __fsub_rn(v.x, smr[(4 * p + 0) * TOK_CTA + off]);
            v.y = __fsub_rn(v.y, smr[(4 * p + 1) * TOK_CTA + off]);
            v.z = __fsub_rn(v.z, smr[(4 * p + 2) * TOK_CTA + off]);
            v.w = __fsub_rn(v.w, smr[(4 * p + 3) * TOK_CTA + off]);
            orow[p] = v;
        }
    }
}

extern "C" void kernel_launch(void* const* d_in, const int* in_sizes, int n_in,
                              void* d_out, int out_size) {
    const float* x;
    const float* cb;
    if (in_sizes[0] == NQ * KCODES * DIM) {
        cb = (const float*)d_in[0];
        x  = (const float*)d_in[1];
    } else {
        x  = (const float*)d_in[0];
        cb = (const float*)d_in[1];
    }
    float* out = (float*)d_out;

    const int smem_bytes = (DIM * TOK_CTA + DIM * TILE + TILE) * sizeof(float);
    cudaFuncSetAttribute(rvq_kernel,
                         cudaFuncAttributeMaxDynamicSharedMemorySize, smem_bytes);

    csq_kernel<<<(NQ * KCODES) / 128, 128>>>(cb);
    rvq_kernel<<<TOKENS / TOK_CTA, CTA, smem_bytes>>>(x, cb, out);
}

// round 6
// speedup vs baseline: 1.5847x; 1.5749x over previous
#include <cuda_runtime.h>

#define NQ      8
#define KCODES  1024
#define DIM     64
#define TOKENS  65536
#define TILE    64          // codes per smem tile
#define CTA     128         // threads per CTA (4 warps)
#define WARPS   4
#define TPW     16          // tokens per warp
#define PAD     18          // padded residual row (bank-friendly)

typedef unsigned long long u64;
typedef unsigned int u32;

__device__ float g_csq[NQ * KCODES];

__device__ __forceinline__ void ffma2(u64& acc, u64 a, u64 b) {
    asm("fma.rn.f32x2 %0, %1, %2, %0;" : "+l"(acc) : "l"(a), "l"(b));
}
__device__ __forceinline__ u64 add2(u64 a, u64 b) {
    u64 r;
    asm("add.rn.f32x2 %0, %1, %2;" : "=l"(r) : "l"(a), "l"(b));
    return r;
}
__device__ __forceinline__ u64 dup2(float v) {
    u64 r;
    asm("mov.b64 %0, {%1, %1};" : "=l"(r) : "f"(v));
    return r;
}
__device__ __forceinline__ u64 pack2(float lo, float hi) {
    u64 r;
    asm("mov.b64 %0, {%1, %2};" : "=l"(r) : "f"(lo), "f"(hi));
    return r;
}
__device__ __forceinline__ void unpack2(float& lo, float& hi, u64 v) {
    asm("mov.b64 {%0, %1}, %2;" : "=f"(lo), "=f"(hi) : "l"(v));
}
// monotone float->u32 (total order), then key = score:code
__device__ __forceinline__ u64 make_key(float s, u32 idx) {
    u32 b = __float_as_uint(s);
    u32 u = b ^ (u32)(((int)b >> 31) | 0x80000000);
    return ((u64)u << 32) | idx;
}

// c_sq[k]: sequential d-ascending fadd(fmul) — bit-exact recipe
__global__ void csq_kernel(const float* __restrict__ cb) {
    int r = blockIdx.x * blockDim.x + threadIdx.x;
    const float4* row = reinterpret_cast<const float4*>(cb + (size_t)r * DIM);
    float s = 0.f;
#pragma unroll
    for (int i = 0; i < DIM / 4; i++) {
        float4 v = row[i];
        s = __fadd_rn(s, __fmul_rn(v.x, v.x));
        s = __fadd_rn(s, __fmul_rn(v.y, v.y));
        s = __fadd_rn(s, __fmul_rn(v.z, v.z));
        s = __fadd_rn(s, __fmul_rn(v.w, v.w));
    }
    g_csq[r] = s;
}

__global__ void __launch_bounds__(CTA)
rvq_kernel(const float* __restrict__ x,
           const float* __restrict__ cb,
           float* __restrict__ out) {
    __shared__ float4 smT4[DIM / 4][TILE];        // [dchunk][code], 16KB
    __shared__ float  scq[TILE];
    __shared__ float  smr[WARPS][DIM][PAD];       // per-warp residuals, 18KB

    const int tid  = threadIdx.x;
    const int wid  = tid >> 5;
    const int lane = tid & 31;
    const int tokenBase = blockIdx.x * (WARPS * TPW) + wid * TPW;

    float (*myr)[PAD] = smr[wid];

    // init residual = x  (lanes cover d = lane, lane+32; one token per iter)
#pragma unroll 1
    for (int t = 0; t < TPW; t++) {
        const float* xr = x + (size_t)(tokenBase + t) * DIM;
        myr[lane][t]      = xr[lane];
        myr[lane + 32][t] = xr[lane + 32];
    }
    __syncwarp();

#pragma unroll 1
    for (int q = 0; q < NQ; q++) {
        const float* cbq = cb + (size_t)q * KCODES * DIM;

        // r_sq per token: lane t (<16) owns token t; sequential fadd(fmul)
        float rs = 0.f;
        if (lane < TPW) {
#pragma unroll
            for (int d = 0; d < DIM; d++) {
                float v = myr[d][lane];
                rs = __fadd_rn(rs, __fmul_rn(v, v));
            }
        }
        u64 rsq2[TPW / 2];
#pragma unroll
        for (int p = 0; p < TPW / 2; p++) {
            float lo = __shfl_sync(0xffffffffu, rs, 2 * p);
            float hi = __shfl_sync(0xffffffffu, rs, 2 * p + 1);
            rsq2[p] = pack2(lo, hi);
        }

        u64 key[TPW];
#pragma unroll
        for (int t = 0; t < TPW; t++) key[t] = 0xFFFFFFFFFFFFFFFFull;

#pragma unroll 1
        for (int c = 0; c < KCODES / TILE; c++) {
            __syncthreads();
            {   // cooperative tile load: [dchunk][code] float4 layout
                int code = tid & 63;
                int half = tid >> 6;                 // 0/1 -> dchunks 0-7 / 8-15
                const float4* src = reinterpret_cast<const float4*>(
                    cbq + (size_t)(c * TILE + code) * DIM) + half * 8;
#pragma unroll
                for (int i = 0; i < 8; i++)
                    smT4[half * 8 + i][code] = src[i];
                if (tid < TILE)
                    scq[tid] = g_csq[q * KCODES + c * TILE + tid];
            }
            __syncthreads();

            u64 acc0[8], acc1[8];
#pragma unroll
            for (int p = 0; p < 8; p++) { acc0[p] = 0ull; acc1[p] = 0ull; }

#pragma unroll 2
            for (int dc = 0; dc < DIM / 4; dc++) {
                float4 cv0 = smT4[dc][lane];         // per-lane distinct LDS.128
                float4 cv1 = smT4[dc][lane + 32];
#pragma unroll
                for (int j = 0; j < 4; j++) {
                    u64 rp[8];
#pragma unroll
                    for (int p = 0; p < 8; p++)      // broadcast LDS.64
                        rp[p] = *reinterpret_cast<const u64*>(
                            &myr[dc * 4 + j][2 * p]);
                    float c0s = (j == 0) ? cv0.x : (j == 1) ? cv0.y
                              : (j == 2) ? cv0.z : cv0.w;
                    float c1s = (j == 0) ? cv1.x : (j == 1) ? cv1.y
                              : (j == 2) ? cv1.z : cv1.w;
                    u64 a0 = dup2(c0s);
                    u64 a1 = dup2(c1s);
#pragma unroll
                    for (int p = 0; p < 8; p++) {
                        ffma2(acc0[p], a0, rp[p]);
                        ffma2(acc1[p], a1, rp[p]);
                    }
                }
            }

            // scores: s = (rsq - 2*dot) + csq   (fma(-2) == fsub(rsq, 2*dot) exactly)
            const u64 NEG2 = 0xC0000000C0000000ull;  // (-2.f, -2.f)
            u64 cs0d = dup2(scq[lane]);
            u64 cs1d = dup2(scq[lane + 32]);
            u32 idx0 = (u32)(c * TILE + lane);
            u32 idx1 = idx0 + 32;
#pragma unroll
            for (int p = 0; p < 8; p++) {
                u64 t0 = rsq2[p]; ffma2(t0, acc0[p], NEG2);
                u64 s0 = add2(t0, cs0d);
                u64 t1 = rsq2[p]; ffma2(t1, acc1[p], NEG2);
                u64 s1 = add2(t1, cs1d);
                float a, b;
                unpack2(a, b, s0);
                u64 k;
                k = make_key(a, idx0); if (k < key[2 * p])     key[2 * p]     = k;
                k = make_key(b, idx0); if (k < key[2 * p + 1]) key[2 * p + 1] = k;
                unpack2(a, b, s1);
                k = make_key(a, idx1); if (k < key[2 * p])     key[2 * p]     = k;
                k = make_key(b, idx1); if (k < key[2 * p + 1]) key[2 * p + 1] = k;
            }
        }

        // cross-lane argmin merge (first-min: equal score -> lower code idx)
#pragma unroll
        for (int off = 16; off >= 1; off >>= 1) {
#pragma unroll
            for (int t = 0; t < TPW; t++) {
                u64 o = __shfl_xor_sync(0xffffffffu, key[t], off);
                if (o < key[t]) key[t] = o;
            }
        }

        // residual update: single fsub per element
#pragma unroll 1
        for (int t = 0; t < TPW; t++) {
            int bk = (int)(key[t] & 0xFFFFull);
            const float* crow = cbq + (size_t)bk * DIM;
            myr[lane][t]      = __fsub_rn(myr[lane][t],      crow[lane]);
            myr[lane + 32][t] = __fsub_rn(myr[lane + 32][t], crow[lane + 32]);
        }
        __syncwarp();
    }

    // out = x - residual_final
#pragma unroll 1
    for (int t = 0; t < TPW; t++) {
        const float* xr  = x   + (size_t)(tokenBase + t) * DIM;
        float*       orw = out + (size_t)(tokenBase + t) * DIM;
        orw[lane]      = __fsub_rn(xr[lane],      myr[lane][t]);
        orw[lane + 32] = __fsub_rn(xr[lane + 32], myr[lane + 32][t]);
    }
}

extern "C" void kernel_launch(void* const* d_in, const int* in_sizes, int n_in,
                              void* d_out, int out_size) {
    const float* x;
    const float* cb;
    if (in_sizes[0] == NQ * KCODES * DIM) {
        cb = (const float*)d_in[0];
        x  = (const float*)d_in[1];
    } else {
        x  = (const float*)d_in[0];
        cb = (const float*)d_in[1];
    }
    float* out = (float*)d_out;

    csq_kernel<<<(NQ * KCODES) / 128, 128>>>(cb);
    rvq_kernel<<<TOKENS / (WARPS * TPW), CTA>>>(x, cb, out);
}

// round 7
// speedup vs baseline: 1.8486x; 1.1666x over previous
#include <cuda_runtime.h>

#define NQ      8
#define KCODES  1024
#define DIM     64
#define TOKENS  65536
#define TILE    128         // codes per smem tile
#define C       4           // codes per lane (lane, +32, +64, +96)
#define CTA     128         // threads per CTA (4 warps)
#define WARPS   4
#define TPW     16          // tokens per warp
#define PAD     20          // residual row pad: 16B-aligned, modest bank skew

typedef unsigned long long u64;
typedef unsigned int u32;

__device__ float g_csq[NQ * KCODES];

__device__ __forceinline__ void ffma2(u64& acc, u64 a, u64 b) {
    asm("fma.rn.f32x2 %0, %1, %2, %0;" : "+l"(acc) : "l"(a), "l"(b));
}
__device__ __forceinline__ u64 add2(u64 a, u64 b) {
    u64 r;
    asm("add.rn.f32x2 %0, %1, %2;" : "=l"(r) : "l"(a), "l"(b));
    return r;
}
__device__ __forceinline__ u64 dup2(float v) {
    u64 r;
    asm("mov.b64 %0, {%1, %1};" : "=l"(r) : "f"(v));
    return r;
}
__device__ __forceinline__ u64 pack2(float lo, float hi) {
    u64 r;
    asm("mov.b64 %0, {%1, %2};" : "=l"(r) : "f"(lo), "f"(hi));
    return r;
}
__device__ __forceinline__ void unpack2(float& lo, float& hi, u64 v) {
    asm("mov.b64 {%0, %1}, %2;" : "=f"(lo), "=f"(hi) : "l"(v));
}
// monotone float->u32, key = score:code  (min key == first-min argmin)
__device__ __forceinline__ u64 make_key(float s, u32 idx) {
    u32 b = __float_as_uint(s);
    u32 u = b ^ (u32)(((int)b >> 31) | 0x80000000);
    return ((u64)u << 32) | idx;
}

__global__ void csq_kernel(const float* __restrict__ cb) {
    int r = blockIdx.x * blockDim.x + threadIdx.x;
    const float4* row = reinterpret_cast<const float4*>(cb + (size_t)r * DIM);
    float s = 0.f;
#pragma unroll
    for (int i = 0; i < DIM / 4; i++) {
        float4 v = row[i];
        s = __fadd_rn(s, __fmul_rn(v.x, v.x));
        s = __fadd_rn(s, __fmul_rn(v.y, v.y));
        s = __fadd_rn(s, __fmul_rn(v.z, v.z));
        s = __fadd_rn(s, __fmul_rn(v.w, v.w));
    }
    g_csq[r] = s;
}

__global__ void __launch_bounds__(CTA)
rvq_kernel(const float* __restrict__ x,
           const float* __restrict__ cb,
           float* __restrict__ out) {
    extern __shared__ float sm[];
    // layout: smT4 [DIM/4][TILE] float4 (32KB) | scq [TILE] | smr [WARPS][DIM][PAD]
    float4* smT4 = reinterpret_cast<float4*>(sm);
    float*  scq  = sm + (DIM / 4) * TILE * 4;
    float*  smr_ = scq + TILE;

    const int tid  = threadIdx.x;
    const int wid  = tid >> 5;
    const int lane = tid & 31;
    const int tokenBase = blockIdx.x * (WARPS * TPW) + wid * TPW;

    float* myr = smr_ + wid * DIM * PAD;   // [DIM][PAD]

    // init residual = x
#pragma unroll 1
    for (int t = 0; t < TPW; t++) {
        const float* xr = x + (size_t)(tokenBase + t) * DIM;
        myr[lane * PAD + t]        = xr[lane];
        myr[(lane + 32) * PAD + t] = xr[lane + 32];
    }
    __syncwarp();

#pragma unroll 1
    for (int q = 0; q < NQ; q++) {
        const float* cbq = cb + (size_t)q * KCODES * DIM;

        // r_sq per token (lane t<16 owns token t): sequential fadd(fmul)
        float rs = 0.f;
        if (lane < TPW) {
#pragma unroll
            for (int d = 0; d < DIM; d++) {
                float v = myr[d * PAD + lane];
                rs = __fadd_rn(rs, __fmul_rn(v, v));
            }
        }
        u64 rsq2[TPW / 2];
#pragma unroll
        for (int p = 0; p < TPW / 2; p++) {
            float lo = __shfl_sync(0xffffffffu, rs, 2 * p);
            float hi = __shfl_sync(0xffffffffu, rs, 2 * p + 1);
            rsq2[p] = pack2(lo, hi);
        }

        u64 key[TPW];
#pragma unroll
        for (int t = 0; t < TPW; t++) key[t] = 0xFFFFFFFFFFFFFFFFull;

#pragma unroll 1
        for (int c = 0; c < KCODES / TILE; c++) {
            __syncthreads();
            {   // tile load: [dchunk][code] float4; thread pair covers one code
                int code = tid & 127;
                int half = tid >> 7;                 // 0: all threads (CTA=128 -> half=0)
                const float4* src = reinterpret_cast<const float4*>(
                    cbq + (size_t)(c * TILE + code) * DIM);
#pragma unroll
                for (int i = 0; i < DIM / 4; i++)
                    smT4[i * TILE + code] = src[i];
                if (tid < TILE)
                    scq[tid] = g_csq[q * KCODES + c * TILE + tid];
                (void)half;
            }
            __syncthreads();

            u64 acc[C][8];
#pragma unroll
            for (int cc = 0; cc < C; cc++)
#pragma unroll
                for (int p = 0; p < 8; p++) acc[cc][p] = 0ull;

#pragma unroll 1
            for (int dc = 0; dc < DIM / 4; dc++) {
                float4 cv[C];                        // per-lane distinct LDS.128
#pragma unroll
                for (int cc = 0; cc < C; cc++)
                    cv[cc] = smT4[dc * TILE + lane + 32 * cc];
#pragma unroll
                for (int j = 0; j < 4; j++) {
                    // rp: 16 tokens = 8 u64, loaded as 4x LDS.128 broadcast
                    const ulonglong2* rrow = reinterpret_cast<const ulonglong2*>(
                        myr + (dc * 4 + j) * PAD);
                    ulonglong2 r0 = rrow[0];
                    ulonglong2 r1 = rrow[1];
                    ulonglong2 r2 = rrow[2];
                    ulonglong2 r3 = rrow[3];
#pragma unroll
                    for (int cc = 0; cc < C; cc++) {
                        float cs = (j == 0) ? cv[cc].x : (j == 1) ? cv[cc].y
                                 : (j == 2) ? cv[cc].z : cv[cc].w;
                        u64 a = dup2(cs);
                        ffma2(acc[cc][0], a, r0.x);
                        ffma2(acc[cc][1], a, r0.y);
                        ffma2(acc[cc][2], a, r1.x);
                        ffma2(acc[cc][3], a, r1.y);
                        ffma2(acc[cc][4], a, r2.x);
                        ffma2(acc[cc][5], a, r2.y);
                        ffma2(acc[cc][6], a, r3.x);
                        ffma2(acc[cc][7], a, r3.y);
                    }
                }
            }

            // scores: s = (rsq - 2*dot) + csq ; fma(-2,dot,rsq) == fsub(rsq,2*dot)
            const u64 NEG2 = 0xC0000000C0000000ull;
#pragma unroll
            for (int cc = 0; cc < C; cc++) {
                u64 csd  = dup2(scq[lane + 32 * cc]);
                u32 idx  = (u32)(c * TILE + lane + 32 * cc);
#pragma unroll
                for (int p = 0; p < 8; p++) {
                    u64 t0 = rsq2[p];
                    ffma2(t0, acc[cc][p], NEG2);
                    u64 s0 = add2(t0, csd);
                    float a, b;
                    unpack2(a, b, s0);
                    u64 k;
                    k = make_key(a, idx); if (k < key[2 * p])     key[2 * p]     = k;
                    k = make_key(b, idx); if (k < key[2 * p + 1]) key[2 * p + 1] = k;
                }
            }
        }

        // cross-lane argmin merge (min key = first-min)
#pragma unroll
        for (int off = 16; off >= 1; off >>= 1) {
#pragma unroll
            for (int t = 0; t < TPW; t++) {
                u64 o = __shfl_xor_sync(0xffffffffu, key[t], off);
                if (o < key[t]) key[t] = o;
            }
        }

        // residual update: single fsub per element
#pragma unroll 1
        for (int t = 0; t < TPW; t++) {
            int bk = (int)(key[t] & 0xFFFFull);
            const float* crow = cbq + (size_t)bk * DIM;
            myr[lane * PAD + t]        = __fsub_rn(myr[lane * PAD + t],        crow[lane]);
            myr[(lane + 32) * PAD + t] = __fsub_rn(myr[(lane + 32) * PAD + t], crow[lane + 32]);
        }
        __syncwarp();
    }

    // out = x - residual_final
#pragma unroll 1
    for (int t = 0; t < TPW; t++) {
        const float* xr  = x   + (size_t)(tokenBase + t) * DIM;
        float*       orw = out + (size_t)(tokenBase + t) * DIM;
        orw[lane]      = __fsub_rn(xr[lane],      myr[lane * PAD + t]);
        orw[lane + 32] = __fsub_rn(xr[lane + 32], myr[(lane + 32) * PAD + t]);
    }
}

extern "C" void kernel_launch(void* const* d_in, const int* in_sizes, int n_in,
                              void* d_out, int out_size) {
    const float* x;
    const float* cb;
    if (in_sizes[0] == NQ * KCODES * DIM) {
        cb = (const float*)d_in[0];
        x  = (const float*)d_in[1];
    } else {
        x  = (const float*)d_in[0];
        cb = (const float*)d_in[1];
    }
    float* out = (float*)d_out;

    const int smem_bytes = ((DIM / 4) * TILE * 4 + TILE + WARPS * DIM * PAD)
                           * (int)sizeof(float);
    cudaFuncSetAttribute(rvq_kernel,
                         cudaFuncAttributeMaxDynamicSharedMemorySize, smem_bytes);

    csq_kernel<<<(NQ * KCODES) / 128, 128>>>(cb);
    rvq_kernel<<<TOKENS / (WARPS * TPW), CTA, smem_bytes>>>(x, cb, out);
}